// round 1
// baseline (speedup 1.0000x reference)
#include <cuda_runtime.h>
#include <math.h>

#define Bb 4
#define Ss 4096
#define Dd 1024
#define Mm (Bb*Ss)      // 16384 rows
#define NCHUNK 64
#define CLEN (Ss/NCHUNK) // 64

// Scratch (device globals: allocation-free, graph-capture safe)
__device__ float g_dt[(size_t)Mm*Dd];     // 64 MB
__device__ float g_gate[(size_t)Mm*Dd];   // 64 MB
__device__ float g_inp[(size_t)Mm*Dd];    // 64 MB (becomes h in-place)
__device__ float g_Ac[Bb*NCHUNK*Dd];
__device__ float g_Bc[Bb*NCHUNK*Dd];
__device__ float g_carry[Bb*NCHUNK*Dd];

__device__ __forceinline__ float softplusf(float v) {
    return (v > 20.0f) ? v : log1pf(expf(v));
}

// Generic tiled SIMT fp32 GEMM: out[m,n] = sum_k A[m,k] * W[n,k]
// MODE 0: writes g_dt = softplus(acc + dt_b[n]);       aux1 = dt_b
// MODE 1: Bp = acc; reads g_dt; writes g_gate, g_inp;  aux2 = A_log, aux3 = h0 (A==x)
// MODE 2: A-matrix is g_inp (h); out = acc + Dp[n]*x;  aux1 = Dp, aux2 = x
template<int MODE>
__global__ __launch_bounds__(256, 2)
void gemm_kernel(const float* __restrict__ A, const float* __restrict__ W,
                 float* __restrict__ out,
                 const float* __restrict__ aux1,
                 const float* __restrict__ aux2,
                 const float* __restrict__ aux3)
{
    const int BM = 128, BN = 128, BK = 16;
    __shared__ float As[BK][BM];
    __shared__ float Ws[BK][BN];

    const float* Ap = (MODE == 2) ? (const float*)g_inp : A;

    const int tid = threadIdx.x;
    const int bm = blockIdx.y * BM;
    const int bn = blockIdx.x * BN;
    const int tx = tid & 15;       // 0..15
    const int ty = tid >> 4;       // 0..15

    float acc[8][8];
    #pragma unroll
    for (int i = 0; i < 8; i++)
        #pragma unroll
        for (int j = 0; j < 8; j++) acc[i][j] = 0.0f;

    for (int k0 = 0; k0 < Dd; k0 += BK) {
        // Load A tile (128 rows x 16 cols), transpose into As[k][m]
        #pragma unroll
        for (int i = 0; i < 2; i++) {
            int f = tid + i * 256;              // 0..511 float4 slots
            int row = f >> 2;
            int kc = (f & 3) * 4;
            float4 v = *(const float4*)&Ap[(size_t)(bm + row) * Dd + k0 + kc];
            As[kc + 0][row] = v.x;
            As[kc + 1][row] = v.y;
            As[kc + 2][row] = v.z;
            As[kc + 3][row] = v.w;
        }
        // Load W tile (128 rows x 16 cols), transpose into Ws[k][n]
        #pragma unroll
        for (int i = 0; i < 2; i++) {
            int f = tid + i * 256;
            int row = f >> 2;
            int kc = (f & 3) * 4;
            float4 v = *(const float4*)&W[(size_t)(bn + row) * Dd + k0 + kc];
            Ws[kc + 0][row] = v.x;
            Ws[kc + 1][row] = v.y;
            Ws[kc + 2][row] = v.z;
            Ws[kc + 3][row] = v.w;
        }
        __syncthreads();

        #pragma unroll
        for (int k = 0; k < BK; k++) {
            float ra[8], rw[8];
            #pragma unroll
            for (int i = 0; i < 4; i++) {
                ((float4*)ra)[0] = *(const float4*)&As[k][ty * 8];
                ((float4*)ra)[1] = *(const float4*)&As[k][ty * 8 + 4];
                ((float4*)rw)[0] = *(const float4*)&Ws[k][tx * 8];
                ((float4*)rw)[1] = *(const float4*)&Ws[k][tx * 8 + 4];
                break;
            }
            #pragma unroll
            for (int i = 0; i < 8; i++)
                #pragma unroll
                for (int j = 0; j < 8; j++)
                    acc[i][j] += ra[i] * rw[j];
        }
        __syncthreads();
    }

    // Epilogue
    #pragma unroll
    for (int i = 0; i < 8; i++) {
        int m = bm + ty * 8 + i;
        size_t rowoff = (size_t)m * Dd;
        #pragma unroll
        for (int j = 0; j < 8; j++) {
            int n = bn + tx * 8 + j;
            float v = acc[i][j];
            if (MODE == 0) {
                g_dt[rowoff + n] = softplusf(v + aux1[n]);
            } else if (MODE == 1) {
                float dt = g_dt[rowoff + n];
                float a  = -expf(aux2[n]);          // A = -exp(A_log)
                float g  = expf(dt * a);            // gate
                float xv = A[rowoff + n];           // x[b,s,n]
                float in = dt * v * xv;             // dt * Bp * x
                int s = m & (Ss - 1);
                if (s == 0) {
                    int b = m / Ss;
                    in += g * aux3[(size_t)b * Dd + n];  // fold h0
                }
                g_gate[rowoff + n] = g;
                g_inp[rowoff + n]  = in;
            } else {
                out[rowoff + n] = v + aux1[n] * aux2[rowoff + n];  // + D*x
            }
        }
    }
}

// Scan pass 1: per-chunk aggregates (a = prod gate, h = local scan end)
__global__ void scan_pass1()
{
    int idx = blockIdx.x * blockDim.x + threadIdx.x;   // b*NCHUNK*D + chunk*D + d
    int d = idx & (Dd - 1);
    int chunk = (idx / Dd) & (NCHUNK - 1);
    int b = idx / (Dd * NCHUNK);
    size_t base = ((size_t)b * Ss + (size_t)chunk * CLEN) * Dd + d;
    float a = 1.0f, h = 0.0f;
    for (int t = 0; t < CLEN; t++) {
        float g  = g_gate[base + (size_t)t * Dd];
        float in = g_inp [base + (size_t)t * Dd];
        a *= g;
        h = g * h + in;
    }
    g_Ac[idx] = a;
    g_Bc[idx] = h;
}

// Scan pass 2: serial carry across chunks
__global__ void scan_pass2()
{
    int idx = blockIdx.x * blockDim.x + threadIdx.x;   // b*D + d
    int d = idx & (Dd - 1);
    int b = idx / Dd;
    float c = 0.0f;
    for (int ch = 0; ch < NCHUNK; ch++) {
        int o = (b * NCHUNK + ch) * Dd + d;
        g_carry[o] = c;                 // h entering this chunk
        c = g_Ac[o] * c + g_Bc[o];
    }
}

// Scan pass 3: re-apply with carry-in, write h over g_inp in-place
__global__ void scan_pass3()
{
    int idx = blockIdx.x * blockDim.x + threadIdx.x;
    int d = idx & (Dd - 1);
    int chunk = (idx / Dd) & (NCHUNK - 1);
    int b = idx / (Dd * NCHUNK);
    size_t base = ((size_t)b * Ss + (size_t)chunk * CLEN) * Dd + d;
    float h = g_carry[idx];
    for (int t = 0; t < CLEN; t++) {
        size_t o = base + (size_t)t * Dd;
        float g  = g_gate[o];
        float in = g_inp[o];
        h = g * h + in;
        g_inp[o] = h;                   // h_all
    }
}

extern "C" void kernel_launch(void* const* d_in, const int* in_sizes, int n_in,
                              void* d_out, int out_size)
{
    const float* x     = (const float*)d_in[0];
    const float* h0    = (const float*)d_in[1];
    const float* dt_w  = (const float*)d_in[2];
    const float* dt_b  = (const float*)d_in[3];
    const float* A_log = (const float*)d_in[4];
    const float* B_w   = (const float*)d_in[5];
    const float* C_w   = (const float*)d_in[6];
    const float* Dp    = (const float*)d_in[7];
    float* out = (float*)d_out;

    dim3 grid(Dd / 128, Mm / 128);
    dim3 blk(256);

    // 1) dt = softplus(x @ dt_w^T + dt_b)  -> g_dt
    gemm_kernel<0><<<grid, blk>>>(x, dt_w, nullptr, dt_b, nullptr, nullptr);
    // 2) Bp = x @ B_w^T; gate/inputs epilogue -> g_gate, g_inp
    gemm_kernel<1><<<grid, blk>>>(x, B_w, nullptr, nullptr, A_log, h0);
    // 3) chunked associative scan: h_t = gate_t*h_{t-1} + in_t  (in-place into g_inp)
    scan_pass1<<<(Bb * NCHUNK * Dd) / 256, 256>>>();
    scan_pass2<<<(Bb * Dd) / 256, 256>>>();
    scan_pass3<<<(Bb * NCHUNK * Dd) / 256, 256>>>();
    // 4) out = h @ C_w^T + D*x
    gemm_kernel<2><<<grid, blk>>>(nullptr, C_w, out, Dp, x, nullptr);
}

// round 3
// speedup vs baseline: 3.0318x; 3.0318x over previous
#include <cuda_runtime.h>
#include <cuda_bf16.h>
#include <math.h>
#include <stdint.h>

#define Bb 4
#define Ss 4096
#define Dd 1024
#define Mm (Bb*Ss)       // 16384
#define NCHUNK 64
#define CLEN (Ss/NCHUNK) // 64

#define BM 128
#define BN 128
#define BK 32
#define NITER (Dd/BK)        // 32
#define STAGE_BYTES 32768    // AH 8K | AL 8K | WH 8K | WL 8K
#define NSTAGE 3
#define SMEM_DYN (NSTAGE*STAGE_BYTES)

// ---------------- scratch (device globals) ----------------
__device__ float g_dt[(size_t)Mm*Dd];
__device__ float g_gate[(size_t)Mm*Dd];
__device__ float g_inp[(size_t)Mm*Dd];
__device__ float g_Ac[Bb*NCHUNK*Dd];
__device__ float g_Bc[Bb*NCHUNK*Dd];
__device__ float g_carry[Bb*NCHUNK*Dd];

__device__ __align__(16) __nv_bfloat16 g_xhi[(size_t)Mm*Dd];
__device__ __align__(16) __nv_bfloat16 g_xlo[(size_t)Mm*Dd];
__device__ __align__(16) __nv_bfloat16 g_hhi[(size_t)Mm*Dd];
__device__ __align__(16) __nv_bfloat16 g_hlo[(size_t)Mm*Dd];
__device__ __align__(16) __nv_bfloat16 g_wh[3][(size_t)Dd*Dd];
__device__ __align__(16) __nv_bfloat16 g_wl[3][(size_t)Dd*Dd];

// ---------------- asm helpers (all plain sm_80-era, no 'a' features) ----------------
__device__ __forceinline__ uint32_t smem_u32(const void* p) {
    uint32_t a;
    asm("{ .reg .u64 t; cvta.to.shared.u64 t, %1; cvt.u32.u64 %0, t; }" : "=r"(a) : "l"(p));
    return a;
}

#define CP_ASYNC16(s, g) \
    asm volatile("cp.async.cg.shared.global [%0], [%1], 16;" :: "r"(s), "l"(g))
#define CP_COMMIT() asm volatile("cp.async.commit_group;")
#define CP_WAIT2()  asm volatile("cp.async.wait_group 2;")

#define LDSM_X4(r0, r1, r2, r3, addr) \
    asm volatile("ldmatrix.sync.aligned.m8n8.x4.shared.b16 {%0,%1,%2,%3}, [%4];" \
        : "=r"(r0), "=r"(r1), "=r"(r2), "=r"(r3) : "r"(addr))

#define MMA_BF16(c, a, b0, b1) \
    asm volatile("mma.sync.aligned.m16n8k16.row.col.f32.bf16.bf16.f32 " \
        "{%0,%1,%2,%3}, {%4,%5,%6,%7}, {%8,%9}, {%0,%1,%2,%3};" \
        : "+f"((c)[0]), "+f"((c)[1]), "+f"((c)[2]), "+f"((c)[3]) \
        : "r"((a)[0]), "r"((a)[1]), "r"((a)[2]), "r"((a)[3]), "r"(b0), "r"(b1))

__device__ __forceinline__ float softplusf(float v) {
    return (v > 20.0f) ? v : log1pf(expf(v));
}

// smem offset for (row, 16B-chunk c): 64B rows, XOR swizzle for conflict-free ldmatrix
__device__ __forceinline__ uint32_t swz(int row, int c) {
    return (uint32_t)(row * 64 + ((c ^ ((row >> 1) & 3)) << 4));
}

// ---------------- bf16 hi/lo split conversion ----------------
// DST 0: x -> g_xhi/g_xlo ; DST 1..3: dt_w/B_w/C_w -> g_wh[k]/g_wl[k]
template<int DST>
__global__ void conv_split(const float* __restrict__ src)
{
    size_t i = ((size_t)blockIdx.x * blockDim.x + threadIdx.x) * 4;
    float4 v = *(const float4*)(src + i);
    __nv_bfloat16* hi;
    __nv_bfloat16* lo;
    if (DST == 0)      { hi = g_xhi;   lo = g_xlo;   }
    else if (DST == 1) { hi = g_wh[0]; lo = g_wl[0]; }
    else if (DST == 2) { hi = g_wh[1]; lo = g_wl[1]; }
    else               { hi = g_wh[2]; lo = g_wl[2]; }
    __nv_bfloat162 ph0 = __floats2bfloat162_rn(v.x, v.y);
    __nv_bfloat162 ph1 = __floats2bfloat162_rn(v.z, v.w);
    __nv_bfloat162 pl0 = __floats2bfloat162_rn(v.x - __low2float(ph0), v.y - __high2float(ph0));
    __nv_bfloat162 pl1 = __floats2bfloat162_rn(v.z - __low2float(ph1), v.w - __high2float(ph1));
    *(__nv_bfloat162*)(hi + i)     = ph0;
    *(__nv_bfloat162*)(hi + i + 2) = ph1;
    *(__nv_bfloat162*)(lo + i)     = pl0;
    *(__nv_bfloat162*)(lo + i + 2) = pl1;
}

// ---------------- bf16-split tensor-core GEMM ----------------
// out[m,n] = sum_k A[m,k] * W[n,k]  (A = x for MODE 0/1, A = h for MODE 2; W = g_wh/wl[MODE])
// MODE 0: g_dt = softplus(acc + dt_b[n])                          aux1 = dt_b
// MODE 1: gate/inputs epilogue                                    aux2 = A_log, aux3 = h0, xptr = x
// MODE 2: out = acc + Dp[n]*x                                     aux1 = Dp, xptr = x
template<int MODE>
__global__ __launch_bounds__(256)
void gemm_bf16(float* __restrict__ out,
               const float* __restrict__ aux1, const float* __restrict__ aux2,
               const float* __restrict__ aux3, const float* __restrict__ xptr)
{
    extern __shared__ char smem[];
    const __nv_bfloat16* __restrict__ Ahi = (MODE == 2) ? g_hhi : g_xhi;
    const __nv_bfloat16* __restrict__ Alo = (MODE == 2) ? g_hlo : g_xlo;
    const __nv_bfloat16* __restrict__ Whi = g_wh[MODE];
    const __nv_bfloat16* __restrict__ Wlo = g_wl[MODE];

    const int tid = threadIdx.x;
    const int wid = tid >> 5, lane = tid & 31;
    const int warpm = wid >> 2, warpn = wid & 3;      // 2 x 4 warp grid, 64x32 per warp
    const int bm = blockIdx.y * BM, bn = blockIdx.x * BN;
    const uint32_t sbase = smem_u32(smem);

    float acc[4][4][4];
    #pragma unroll
    for (int a = 0; a < 4; a++)
        #pragma unroll
        for (int b = 0; b < 4; b++)
            #pragma unroll
            for (int c = 0; c < 4; c++) acc[a][b][c] = 0.0f;

    auto load_stage = [&](int s, int it) {
        uint32_t st = sbase + (uint32_t)s * STAGE_BYTES;
        int k0 = it * BK;
        #pragma unroll
        for (int p = 0; p < 2; p++) {
            int lin = tid + p * 256;       // 0..511 chunks per array
            int row = lin >> 2, c = lin & 3;
            uint32_t soff = swz(row, c);
            size_t ga = (size_t)(bm + row) * Dd + k0 + c * 8;
            size_t gw = (size_t)(bn + row) * Dd + k0 + c * 8;
            CP_ASYNC16(st + soff,         Ahi + ga);
            CP_ASYNC16(st + 8192  + soff, Alo + ga);
            CP_ASYNC16(st + 16384 + soff, Whi + gw);
            CP_ASYNC16(st + 24576 + soff, Wlo + gw);
        }
        CP_COMMIT();
    };

    load_stage(0, 0);
    load_stage(1, 1);

    for (int i = 0; i < NITER; i++) {
        __syncthreads();                       // slot (i+2)%3 free for overwrite
        if (i + 2 < NITER) load_stage((i + 2) % NSTAGE, i + 2);
        else CP_COMMIT();                      // keep group count aligned
        CP_WAIT2();                            // stage i data arrived (this thread)
        __syncthreads();                       // ... and visible to all warps

        uint32_t st = sbase + (uint32_t)(i % NSTAGE) * STAGE_BYTES;
        #pragma unroll
        for (int kk = 0; kk < 2; kk++) {       // two k16 steps per BK=32 stage
            uint32_t ah[4][4], bh[2][4], bl[2][4];
            #pragma unroll
            for (int mi = 0; mi < 4; mi++) {
                int row = warpm * 64 + mi * 16 + (lane & 15);
                int c = kk * 2 + (lane >> 4);
                LDSM_X4(ah[mi][0], ah[mi][1], ah[mi][2], ah[mi][3], st + swz(row, c));
            }
            #pragma unroll
            for (int pr = 0; pr < 2; pr++) {
                int row = warpn * 32 + pr * 16 + (lane & 7) + (((lane >> 4) & 1) << 3);
                int c = kk * 2 + ((lane >> 3) & 1);
                LDSM_X4(bh[pr][0], bh[pr][1], bh[pr][2], bh[pr][3], st + 16384 + swz(row, c));
                LDSM_X4(bl[pr][0], bl[pr][1], bl[pr][2], bl[pr][3], st + 24576 + swz(row, c));
            }
            #pragma unroll
            for (int mi = 0; mi < 4; mi++)
                #pragma unroll
                for (int ni = 0; ni < 4; ni++) {
                    MMA_BF16(acc[mi][ni], ah[mi], bh[ni >> 1][(ni & 1) * 2], bh[ni >> 1][(ni & 1) * 2 + 1]);
                    MMA_BF16(acc[mi][ni], ah[mi], bl[ni >> 1][(ni & 1) * 2], bl[ni >> 1][(ni & 1) * 2 + 1]);
                }
            uint32_t al[4][4];
            #pragma unroll
            for (int mi = 0; mi < 4; mi++) {
                int row = warpm * 64 + mi * 16 + (lane & 15);
                int c = kk * 2 + (lane >> 4);
                LDSM_X4(al[mi][0], al[mi][1], al[mi][2], al[mi][3], st + 8192 + swz(row, c));
            }
            #pragma unroll
            for (int mi = 0; mi < 4; mi++)
                #pragma unroll
                for (int ni = 0; ni < 4; ni++)
                    MMA_BF16(acc[mi][ni], al[mi], bh[ni >> 1][(ni & 1) * 2], bh[ni >> 1][(ni & 1) * 2 + 1]);
        }
    }

    // ---------------- epilogue ----------------
    const int mb0 = bm + warpm * 64;
    const int nb0 = bn + warpn * 32;
    #pragma unroll
    for (int mi = 0; mi < 4; mi++) {
        #pragma unroll
        for (int r = 0; r < 2; r++) {
            int m = mb0 + mi * 16 + (lane >> 2) + r * 8;
            size_t off = (size_t)m * Dd;
            #pragma unroll
            for (int ni = 0; ni < 4; ni++) {
                int n = nb0 + ni * 8 + (lane & 3) * 2;
                float v0 = acc[mi][ni][r * 2], v1 = acc[mi][ni][r * 2 + 1];
                if (MODE == 0) {
                    float2 bv = *(const float2*)&aux1[n];
                    float2 o;
                    o.x = softplusf(v0 + bv.x);
                    o.y = softplusf(v1 + bv.y);
                    *(float2*)&g_dt[off + n] = o;
                } else if (MODE == 1) {
                    float2 dt = *(const float2*)&g_dt[off + n];
                    float2 al2 = *(const float2*)&aux2[n];
                    float2 xv = *(const float2*)&xptr[off + n];
                    float2 gv, iv;
                    gv.x = expf(dt.x * (-expf(al2.x)));
                    gv.y = expf(dt.y * (-expf(al2.y)));
                    iv.x = dt.x * v0 * xv.x;
                    iv.y = dt.y * v1 * xv.y;
                    if ((m & (Ss - 1)) == 0) {
                        int b = m / Ss;
                        float2 h0v = *(const float2*)&aux3[(size_t)b * Dd + n];
                        iv.x += gv.x * h0v.x;
                        iv.y += gv.y * h0v.y;
                    }
                    *(float2*)&g_gate[off + n] = gv;
                    *(float2*)&g_inp[off + n] = iv;
                } else {
                    float2 dp = *(const float2*)&aux1[n];
                    float2 xv = *(const float2*)&xptr[off + n];
                    float2 o;
                    o.x = v0 + dp.x * xv.x;
                    o.y = v1 + dp.y * xv.y;
                    *(float2*)&out[off + n] = o;
                }
            }
        }
    }
}

// ---------------- chunked associative scan ----------------
__global__ void scan_pass1()
{
    int idx = blockIdx.x * blockDim.x + threadIdx.x;
    int d = idx & (Dd - 1);
    int chunk = (idx / Dd) & (NCHUNK - 1);
    int b = idx / (Dd * NCHUNK);
    size_t base = ((size_t)b * Ss + (size_t)chunk * CLEN) * Dd + d;
    float a = 1.0f, h = 0.0f;
    for (int t = 0; t < CLEN; t++) {
        float g  = g_gate[base + (size_t)t * Dd];
        float in = g_inp [base + (size_t)t * Dd];
        a *= g;
        h = g * h + in;
    }
    g_Ac[idx] = a;
    g_Bc[idx] = h;
}

__global__ void scan_pass2()
{
    int idx = blockIdx.x * blockDim.x + threadIdx.x;   // b*D + d
    int d = idx & (Dd - 1);
    int b = idx / Dd;
    float c = 0.0f;
    for (int ch = 0; ch < NCHUNK; ch++) {
        int o = (b * NCHUNK + ch) * Dd + d;
        g_carry[o] = c;
        c = g_Ac[o] * c + g_Bc[o];
    }
}

__global__ void scan_pass3()
{
    int idx = blockIdx.x * blockDim.x + threadIdx.x;
    int d = idx & (Dd - 1);
    int chunk = (idx / Dd) & (NCHUNK - 1);
    int b = idx / (Dd * NCHUNK);
    size_t base = ((size_t)b * Ss + (size_t)chunk * CLEN) * Dd + d;
    float h = g_carry[idx];
    for (int t = 0; t < CLEN; t++) {
        size_t o = base + (size_t)t * Dd;
        h = g_gate[o] * h + g_inp[o];
        __nv_bfloat16 hh = __float2bfloat16(h);
        g_hhi[o] = hh;
        g_hlo[o] = __float2bfloat16(h - __bfloat162float(hh));
    }
}

extern "C" void kernel_launch(void* const* d_in, const int* in_sizes, int n_in,
                              void* d_out, int out_size)
{
    const float* x     = (const float*)d_in[0];
    const float* h0    = (const float*)d_in[1];
    const float* dt_w  = (const float*)d_in[2];
    const float* dt_b  = (const float*)d_in[3];
    const float* A_log = (const float*)d_in[4];
    const float* B_w   = (const float*)d_in[5];
    const float* C_w   = (const float*)d_in[6];
    const float* Dp    = (const float*)d_in[7];
    float* out = (float*)d_out;

    cudaFuncSetAttribute(gemm_bf16<0>, cudaFuncAttributeMaxDynamicSharedMemorySize, SMEM_DYN);
    cudaFuncSetAttribute(gemm_bf16<1>, cudaFuncAttributeMaxDynamicSharedMemorySize, SMEM_DYN);
    cudaFuncSetAttribute(gemm_bf16<2>, cudaFuncAttributeMaxDynamicSharedMemorySize, SMEM_DYN);

    // bf16 hi/lo splits
    conv_split<0><<<((size_t)Mm * Dd) / 1024, 256>>>(x);
    conv_split<1><<<((size_t)Dd * Dd) / 1024, 256>>>(dt_w);
    conv_split<2><<<((size_t)Dd * Dd) / 1024, 256>>>(B_w);
    conv_split<3><<<((size_t)Dd * Dd) / 1024, 256>>>(C_w);

    dim3 grid(Dd / BN, Mm / BM);   // (8, 128)
    dim3 blk(256);

    gemm_bf16<0><<<grid, blk, SMEM_DYN>>>(nullptr, dt_b, nullptr, nullptr, nullptr);
    gemm_bf16<1><<<grid, blk, SMEM_DYN>>>(nullptr, nullptr, A_log, h0, x);
    scan_pass1<<<(Bb * NCHUNK * Dd) / 256, 256>>>();
    scan_pass2<<<(Bb * Dd) / 256, 256>>>();
    scan_pass3<<<(Bb * NCHUNK * Dd) / 256, 256>>>();
    gemm_bf16<2><<<grid, blk, SMEM_DYN>>>(out, Dp, nullptr, nullptr, x);
}

// round 4
// speedup vs baseline: 3.0832x; 1.0169x over previous
#include <cuda_runtime.h>
#include <cuda_bf16.h>
#include <math.h>
#include <stdint.h>

#define Bb 4
#define Ss 4096
#define Dd 1024
#define Mm (Bb*Ss)       // 16384
#define NCHUNK 64
#define CLEN (Ss/NCHUNK) // 64

#define BM 128
#define BN 128
#define BK 32
#define NITER (Dd/BK)        // 32
#define STAGE_BYTES 32768    // AH 8K | AL 8K | WH 8K | WL 8K
#define NSTAGE 3
#define SMEM_DYN (NSTAGE*STAGE_BYTES)

// ---------------- scratch (device globals) ----------------
__device__ float g_dt[(size_t)Mm*Dd];
__device__ float g_gate[(size_t)Mm*Dd];
__device__ float g_inp[(size_t)Mm*Dd];
__device__ float g_Ac[Bb*NCHUNK*Dd];
__device__ float g_Bc[Bb*NCHUNK*Dd];
__device__ float g_carry[Bb*NCHUNK*Dd];

__device__ __align__(16) __nv_bfloat16 g_xhi[(size_t)Mm*Dd];
__device__ __align__(16) __nv_bfloat16 g_xlo[(size_t)Mm*Dd];
__device__ __align__(16) __nv_bfloat16 g_hhi[(size_t)Mm*Dd];
__device__ __align__(16) __nv_bfloat16 g_hlo[(size_t)Mm*Dd];
__device__ __align__(16) __nv_bfloat16 g_wh[3][(size_t)Dd*Dd];
__device__ __align__(16) __nv_bfloat16 g_wl[3][(size_t)Dd*Dd];

// ---------------- asm helpers (portable sm_80-era only) ----------------
__device__ __forceinline__ uint32_t smem_u32(const void* p) {
    uint32_t a;
    asm("{ .reg .u64 t; cvta.to.shared.u64 t, %1; cvt.u32.u64 %0, t; }" : "=r"(a) : "l"(p));
    return a;
}

#define CP_ASYNC16(s, g) \
    asm volatile("cp.async.cg.shared.global [%0], [%1], 16;" :: "r"(s), "l"(g))
#define CP_COMMIT() asm volatile("cp.async.commit_group;")
#define CP_WAIT1()  asm volatile("cp.async.wait_group 1;")
#define CP_WAIT0()  asm volatile("cp.async.wait_group 0;")

#define LDSM_X4(r0, r1, r2, r3, addr) \
    asm volatile("ldmatrix.sync.aligned.m8n8.x4.shared.b16 {%0,%1,%2,%3}, [%4];" \
        : "=r"(r0), "=r"(r1), "=r"(r2), "=r"(r3) : "r"(addr))

#define MMA_BF16(c, a, b0, b1) \
    asm volatile("mma.sync.aligned.m16n8k16.row.col.f32.bf16.bf16.f32 " \
        "{%0,%1,%2,%3}, {%4,%5,%6,%7}, {%8,%9}, {%0,%1,%2,%3};" \
        : "+f"((c)[0]), "+f"((c)[1]), "+f"((c)[2]), "+f"((c)[3]) \
        : "r"((a)[0]), "r"((a)[1]), "r"((a)[2]), "r"((a)[3]), "r"(b0), "r"(b1))

__device__ __forceinline__ float softplusf(float v) {
    return (v > 20.0f) ? v : log1pf(expf(v));
}

// smem offset for (row, 16B-chunk c): 64B rows, XOR swizzle for conflict-free ldmatrix
__device__ __forceinline__ uint32_t swz(int row, int c) {
    return (uint32_t)(row * 64 + ((c ^ ((row >> 1) & 3)) << 4));
}

// ---------------- bf16 hi/lo split conversion ----------------
template<int DST>
__global__ void conv_split(const float* __restrict__ src)
{
    size_t i = ((size_t)blockIdx.x * blockDim.x + threadIdx.x) * 4;
    float4 v = *(const float4*)(src + i);
    __nv_bfloat16* hi;
    __nv_bfloat16* lo;
    if (DST == 0)      { hi = g_xhi;   lo = g_xlo;   }
    else if (DST == 1) { hi = g_wh[0]; lo = g_wl[0]; }
    else if (DST == 2) { hi = g_wh[1]; lo = g_wl[1]; }
    else               { hi = g_wh[2]; lo = g_wl[2]; }
    __nv_bfloat162 ph0 = __floats2bfloat162_rn(v.x, v.y);
    __nv_bfloat162 ph1 = __floats2bfloat162_rn(v.z, v.w);
    __nv_bfloat162 pl0 = __floats2bfloat162_rn(v.x - __low2float(ph0), v.y - __high2float(ph0));
    __nv_bfloat162 pl1 = __floats2bfloat162_rn(v.z - __low2float(ph1), v.w - __high2float(ph1));
    *(__nv_bfloat162*)(hi + i)     = ph0;
    *(__nv_bfloat162*)(hi + i + 2) = ph1;
    *(__nv_bfloat162*)(lo + i)     = pl0;
    *(__nv_bfloat162*)(lo + i + 2) = pl1;
}

// ---------------- bf16-split tensor-core GEMM ----------------
// out[m,n] = sum_k A[m,k] * W[n,k]
// MODE 0: g_dt = softplus(acc + dt_b[n])        aux1 = dt_b
// MODE 1: gate/inputs epilogue                  aux2 = A_log, aux3 = h0, xptr = x
// MODE 2: out = acc + Dp[n]*x                   aux1 = Dp, xptr = x
template<int MODE>
__global__ __launch_bounds__(256, 2)
void gemm_bf16(float* __restrict__ out,
               const float* __restrict__ aux1, const float* __restrict__ aux2,
               const float* __restrict__ aux3, const float* __restrict__ xptr)
{
    extern __shared__ char smem[];
    const __nv_bfloat16* __restrict__ Ahi = (MODE == 2) ? g_hhi : g_xhi;
    const __nv_bfloat16* __restrict__ Alo = (MODE == 2) ? g_hlo : g_xlo;
    const __nv_bfloat16* __restrict__ Whi = g_wh[MODE];
    const __nv_bfloat16* __restrict__ Wlo = g_wl[MODE];

    const int tid = threadIdx.x;
    const int wid = tid >> 5, lane = tid & 31;
    const int warpm = wid >> 2, warpn = wid & 3;      // 2 x 4 warp grid, 64x32 per warp
    const int bm = blockIdx.y * BM, bn = blockIdx.x * BN;
    const uint32_t sbase = smem_u32(smem);

    float acc[4][4][4];
    #pragma unroll
    for (int a = 0; a < 4; a++)
        #pragma unroll
        for (int b = 0; b < 4; b++)
            #pragma unroll
            for (int c = 0; c < 4; c++) acc[a][b][c] = 0.0f;

    auto load_stage = [&](int s, int it) {
        uint32_t st = sbase + (uint32_t)s * STAGE_BYTES;
        int k0 = it * BK;
        #pragma unroll
        for (int p = 0; p < 2; p++) {
            int lin = tid + p * 256;       // 0..511 chunks per array
            int row = lin >> 2, c = lin & 3;
            uint32_t soff = swz(row, c);
            size_t ga = (size_t)(bm + row) * Dd + k0 + c * 8;
            size_t gw = (size_t)(bn + row) * Dd + k0 + c * 8;
            CP_ASYNC16(st + soff,         Ahi + ga);
            CP_ASYNC16(st + 8192  + soff, Alo + ga);
            CP_ASYNC16(st + 16384 + soff, Whi + gw);
            CP_ASYNC16(st + 24576 + soff, Wlo + gw);
        }
        CP_COMMIT();
    };

    load_stage(0, 0);
    load_stage(1, 1);

    for (int i = 0; i < NITER; i++) {
        // group j (data for iter j) is committed at: prologue (j=0,1) or iter j-2.
        // at iter i, last committed group = min(i+1, NITER-1).
        if (i == NITER - 1) CP_WAIT0(); else CP_WAIT1();
        __syncthreads();                        // data visible + slot (i+2)%3 free
        if (i + 2 < NITER) load_stage((i + 2) % NSTAGE, i + 2);

        uint32_t st = sbase + (uint32_t)(i % NSTAGE) * STAGE_BYTES;
        #pragma unroll
        for (int kk = 0; kk < 2; kk++) {       // two k16 steps per BK=32 stage
            uint32_t ah[4][4], bh[2][4], bl[2][4];
            #pragma unroll
            for (int mi = 0; mi < 4; mi++) {
                int row = warpm * 64 + mi * 16 + (lane & 15);
                int c = kk * 2 + (lane >> 4);
                LDSM_X4(ah[mi][0], ah[mi][1], ah[mi][2], ah[mi][3], st + swz(row, c));
            }
            #pragma unroll
            for (int pr = 0; pr < 2; pr++) {
                int row = warpn * 32 + pr * 16 + (lane & 7) + (((lane >> 4) & 1) << 3);
                int c = kk * 2 + ((lane >> 3) & 1);
                LDSM_X4(bh[pr][0], bh[pr][1], bh[pr][2], bh[pr][3], st + 16384 + swz(row, c));
                LDSM_X4(bl[pr][0], bl[pr][1], bl[pr][2], bl[pr][3], st + 24576 + swz(row, c));
            }
            #pragma unroll
            for (int mi = 0; mi < 4; mi++)
                #pragma unroll
                for (int ni = 0; ni < 4; ni++) {
                    MMA_BF16(acc[mi][ni], ah[mi], bh[ni >> 1][(ni & 1) * 2], bh[ni >> 1][(ni & 1) * 2 + 1]);
                    MMA_BF16(acc[mi][ni], ah[mi], bl[ni >> 1][(ni & 1) * 2], bl[ni >> 1][(ni & 1) * 2 + 1]);
                }
            uint32_t al[4][4];
            #pragma unroll
            for (int mi = 0; mi < 4; mi++) {
                int row = warpm * 64 + mi * 16 + (lane & 15);
                int c = kk * 2 + (lane >> 4);
                LDSM_X4(al[mi][0], al[mi][1], al[mi][2], al[mi][3], st + 8192 + swz(row, c));
            }
            #pragma unroll
            for (int mi = 0; mi < 4; mi++)
                #pragma unroll
                for (int ni = 0; ni < 4; ni++)
                    MMA_BF16(acc[mi][ni], al[mi], bh[ni >> 1][(ni & 1) * 2], bh[ni >> 1][(ni & 1) * 2 + 1]);
        }
    }

    // ---------------- epilogue ----------------
    const int mb0 = bm + warpm * 64;
    const int nb0 = bn + warpn * 32;
    #pragma unroll
    for (int mi = 0; mi < 4; mi++) {
        #pragma unroll
        for (int r = 0; r < 2; r++) {
            int m = mb0 + mi * 16 + (lane >> 2) + r * 8;
            size_t off = (size_t)m * Dd;
            #pragma unroll
            for (int ni = 0; ni < 4; ni++) {
                int n = nb0 + ni * 8 + (lane & 3) * 2;
                float v0 = acc[mi][ni][r * 2], v1 = acc[mi][ni][r * 2 + 1];
                if (MODE == 0) {
                    float2 bv = *(const float2*)&aux1[n];
                    float2 o;
                    o.x = softplusf(v0 + bv.x);
                    o.y = softplusf(v1 + bv.y);
                    *(float2*)&g_dt[off + n] = o;
                } else if (MODE == 1) {
                    float2 dt = *(const float2*)&g_dt[off + n];
                    float2 al2 = *(const float2*)&aux2[n];
                    float2 xv = *(const float2*)&xptr[off + n];
                    float2 gv, iv;
                    gv.x = expf(dt.x * (-expf(al2.x)));
                    gv.y = expf(dt.y * (-expf(al2.y)));
                    iv.x = dt.x * v0 * xv.x;
                    iv.y = dt.y * v1 * xv.y;
                    if ((m & (Ss - 1)) == 0) {
                        int b = m / Ss;
                        float2 h0v = *(const float2*)&aux3[(size_t)b * Dd + n];
                        iv.x += gv.x * h0v.x;
                        iv.y += gv.y * h0v.y;
                    }
                    *(float2*)&g_gate[off + n] = gv;
                    *(float2*)&g_inp[off + n] = iv;
                } else {
                    float2 dp = *(const float2*)&aux1[n];
                    float2 xv = *(const float2*)&xptr[off + n];
                    float2 o;
                    o.x = v0 + dp.x * xv.x;
                    o.y = v1 + dp.y * xv.y;
                    *(float2*)&out[off + n] = o;
                }
            }
        }
    }
}

// ---------------- chunked associative scan ----------------
__global__ void scan_pass1()
{
    int idx = blockIdx.x * blockDim.x + threadIdx.x;
    int d = idx & (Dd - 1);
    int chunk = (idx / Dd) & (NCHUNK - 1);
    int b = idx / (Dd * NCHUNK);
    size_t base = ((size_t)b * Ss + (size_t)chunk * CLEN) * Dd + d;
    float a = 1.0f, h = 0.0f;
    #pragma unroll 8
    for (int t = 0; t < CLEN; t++) {
        float g  = g_gate[base + (size_t)t * Dd];
        float in = g_inp [base + (size_t)t * Dd];
        a *= g;
        h = g * h + in;
    }
    g_Ac[idx] = a;
    g_Bc[idx] = h;
}

__global__ void scan_pass2()
{
    int idx = blockIdx.x * blockDim.x + threadIdx.x;   // b*D + d
    int d = idx & (Dd - 1);
    int b = idx / Dd;
    const int base = b * NCHUNK * Dd + d;

    float A0[8], B0[8], A1[8], B1[8];
    #pragma unroll
    for (int j = 0; j < 8; j++) {
        A0[j] = g_Ac[base + j * Dd];
        B0[j] = g_Bc[base + j * Dd];
    }
    float c = 0.0f;
    #pragma unroll
    for (int ch = 0; ch < 8; ch++) {
        if (ch < 7) {
            #pragma unroll
            for (int j = 0; j < 8; j++) {
                A1[j] = g_Ac[base + ((ch + 1) * 8 + j) * Dd];
                B1[j] = g_Bc[base + ((ch + 1) * 8 + j) * Dd];
            }
        }
        #pragma unroll
        for (int j = 0; j < 8; j++) {
            g_carry[base + (ch * 8 + j) * Dd] = c;
            c = A0[j] * c + B0[j];
        }
        #pragma unroll
        for (int j = 0; j < 8; j++) { A0[j] = A1[j]; B0[j] = B1[j]; }
    }
}

__global__ void scan_pass3()
{
    int idx = blockIdx.x * blockDim.x + threadIdx.x;
    int d = idx & (Dd - 1);
    int chunk = (idx / Dd) & (NCHUNK - 1);
    int b = idx / (Dd * NCHUNK);
    size_t base = ((size_t)b * Ss + (size_t)chunk * CLEN) * Dd + d;
    float h = g_carry[idx];
    #pragma unroll 8
    for (int t = 0; t < CLEN; t++) {
        size_t o = base + (size_t)t * Dd;
        h = g_gate[o] * h + g_inp[o];
        __nv_bfloat16 hh = __float2bfloat16(h);
        g_hhi[o] = hh;
        g_hlo[o] = __float2bfloat16(h - __bfloat162float(hh));
    }
}

extern "C" void kernel_launch(void* const* d_in, const int* in_sizes, int n_in,
                              void* d_out, int out_size)
{
    const float* x     = (const float*)d_in[0];
    const float* h0    = (const float*)d_in[1];
    const float* dt_w  = (const float*)d_in[2];
    const float* dt_b  = (const float*)d_in[3];
    const float* A_log = (const float*)d_in[4];
    const float* B_w   = (const float*)d_in[5];
    const float* C_w   = (const float*)d_in[6];
    const float* Dp    = (const float*)d_in[7];
    float* out = (float*)d_out;

    cudaFuncSetAttribute(gemm_bf16<0>, cudaFuncAttributeMaxDynamicSharedMemorySize, SMEM_DYN);
    cudaFuncSetAttribute(gemm_bf16<1>, cudaFuncAttributeMaxDynamicSharedMemorySize, SMEM_DYN);
    cudaFuncSetAttribute(gemm_bf16<2>, cudaFuncAttributeMaxDynamicSharedMemorySize, SMEM_DYN);

    conv_split<0><<<((size_t)Mm * Dd) / 1024, 256>>>(x);
    conv_split<1><<<((size_t)Dd * Dd) / 1024, 256>>>(dt_w);
    conv_split<2><<<((size_t)Dd * Dd) / 1024, 256>>>(B_w);
    conv_split<3><<<((size_t)Dd * Dd) / 1024, 256>>>(C_w);

    dim3 grid(Dd / BN, Mm / BM);   // (8, 128)
    dim3 blk(256);

    gemm_bf16<0><<<grid, blk, SMEM_DYN>>>(nullptr, dt_b, nullptr, nullptr, nullptr);
    gemm_bf16<1><<<grid, blk, SMEM_DYN>>>(nullptr, nullptr, A_log, h0, x);
    scan_pass1<<<(Bb * NCHUNK * Dd) / 256, 256>>>();
    scan_pass2<<<(Bb * Dd) / 256, 256>>>();
    scan_pass3<<<(Bb * NCHUNK * Dd) / 256, 256>>>();
    gemm_bf16<2><<<grid, blk, SMEM_DYN>>>(out, Dp, nullptr, nullptr, x);
}